// round 6
// baseline (speedup 1.0000x reference)
#include <cuda_runtime.h>
#include <cuda_bf16.h>
#include <cstdint>
#include <math.h>

#define N_NODES 100000
#define N_EDGES 1600000
#define D 128
#define NLAYER 3
#define LN_EPS 1e-5f

// ---------------- scratch (static __device__; referenced ONLY in device code) ----------------
__device__ float g_h[N_NODES * D];
__device__ float g_hsum[N_NODES * D];
__device__ float g_z[N_NODES * D];
__device__ float g_z1[N_NODES * D];
__device__ int g_deg[N_NODES];
__device__ int g_off[N_NODES];
__device__ int g_cur[N_NODES];
__device__ int g_col[N_EDGES];
__device__ int g_bsum[128];

// ================= bf16 split helpers =================
__device__ __forceinline__ void split_bf16(float v, __nv_bfloat16& h, __nv_bfloat16& l) {
    h = __float2bfloat16(v);
    l = __float2bfloat16(v - __bfloat162float(h));
}
__device__ __forceinline__ uint32_t pack2(__nv_bfloat16 a, __nv_bfloat16 b) {
    uint32_t r = (uint32_t)__bfloat16_as_ushort(b) << 16 | (uint32_t)__bfloat16_as_ushort(a);
    return r;
}
__device__ __forceinline__ float gelu_exact(float v) {
    return 0.5f * v * (1.0f + erff(v * 0.70710678118654752f));
}

// ================= smem layout for the GEMM =================
// bf16 tiles stored row-major with 136-bf16 rows (68 words) -> conflict-free
// fragment loads: bank = 4*(row&7) + (lane&3), all distinct within a warp.
#define SAK 68                      // words per row (136 bf16)
#define ASZ (128 * SAK * 4)         // 34816 bytes per staged matrix
#define OFF_AHI 0
#define OFF_ALO ASZ
#define OFF_BHI (2 * ASZ)
#define OFF_BLO (3 * ASZ)
#define OFF_RED (4 * ASZ)           // 139264: red[256] + red2[256]
#define SMEM_TC (OFF_RED + 2048)    // 141312 bytes
#define CSTRIDE 132                 // fp32 C-tile row stride (reuses AHI+ALO region)

__device__ __forceinline__ void mma_bf16(float c[4], uint32_t a0, uint32_t a1, uint32_t a2,
                                         uint32_t a3, uint32_t b0, uint32_t b1) {
    asm volatile(
        "mma.sync.aligned.m16n8k16.row.col.f32.bf16.bf16.f32 "
        "{%0,%1,%2,%3}, {%4,%5,%6,%7}, {%8,%9}, {%0,%1,%2,%3};"
        : "+f"(c[0]), "+f"(c[1]), "+f"(c[2]), "+f"(c[3])
        : "r"(a0), "r"(a1), "r"(a2), "r"(a3), "r"(b0), "r"(b1));
}

// ================= tensor-core GEMM (template on epilogue mode) =================
// MODE 0: g_z1 = relu(g_z @ W + b)
// MODE 1: ln+gelu+residual epilogue on (g_z1 @ W + b); updates g_h, g_hsum
// MODE 2: out = g_z @ W + b
template <int MODE>
__global__ void __launch_bounds__(256, 1)
k_gemm_tc(const float* __restrict__ Bw, const float* __restrict__ bias,
          const float* __restrict__ lng, const float* __restrict__ lnb,
          float* __restrict__ out) {
    extern __shared__ char sm[];
    const int tid = threadIdx.x;
    const int wid = tid >> 5;
    const int lane = tid & 31;
    const int bm = blockIdx.x * 128;
    const float* A = (MODE == 1) ? g_z1 : g_z;

    uint32_t* Ahi = (uint32_t*)(sm + OFF_AHI);
    uint32_t* Alo = (uint32_t*)(sm + OFF_ALO);
    uint32_t* Bhi = (uint32_t*)(sm + OFF_BHI);
    uint32_t* Blo = (uint32_t*)(sm + OFF_BLO);

    // --- stage A (row-major M x K), split fp32 -> bf16 hi/lo ---
#pragma unroll
    for (int i = 0; i < 16; i++) {
        int idx = tid + i * 256;       // 0..4095 float4 units
        int m = idx >> 5;
        int c4 = (idx & 31) << 2;
        float4 v = make_float4(0.f, 0.f, 0.f, 0.f);
        int gm = bm + m;
        if (gm < N_NODES) v = *(const float4*)(A + (size_t)gm * 128 + c4);
        __nv_bfloat16 h0, h1, h2, h3, l0, l1, l2, l3;
        split_bf16(v.x, h0, l0);
        split_bf16(v.y, h1, l1);
        split_bf16(v.z, h2, l2);
        split_bf16(v.w, h3, l3);
        int w = m * SAK + (c4 >> 1);
        Ahi[w] = pack2(h0, h1);
        Ahi[w + 1] = pack2(h2, h3);
        Alo[w] = pack2(l0, l1);
        Alo[w + 1] = pack2(l2, l3);
    }
    // --- stage B transposed: Bw[k][n] -> Bt[n][k] bf16 hi/lo ---
    {
        __nv_bfloat16* bh = (__nv_bfloat16*)(sm + OFF_BHI);
        __nv_bfloat16* bl = (__nv_bfloat16*)(sm + OFF_BLO);
#pragma unroll
        for (int i = 0; i < 16; i++) {
            int idx = tid + i * 256;
            int k = idx >> 5;
            int n4 = (idx & 31) << 2;
            float4 v = *(const float4*)(Bw + (size_t)k * 128 + n4);
            float vv[4] = {v.x, v.y, v.z, v.w};
#pragma unroll
            for (int e = 0; e < 4; e++) {
                __nv_bfloat16 h, l;
                split_bf16(vv[e], h, l);
                bh[(n4 + e) * 136 + k] = h;
                bl[(n4 + e) * 136 + k] = l;
            }
        }
    }
    __syncthreads();

    // --- MMA: warp wid covers rows mw..mw+63, cols nw..nw+31 ---
    const int g = lane >> 2, tg = lane & 3;
    const int mw = (wid & 1) * 64;
    const int nw = (wid >> 1) * 32;
    float c[4][4][4];
#pragma unroll
    for (int mt = 0; mt < 4; mt++)
#pragma unroll
        for (int nt = 0; nt < 4; nt++)
#pragma unroll
            for (int e = 0; e < 4; e++) c[mt][nt][e] = 0.f;

#pragma unroll
    for (int p = 0; p < 3; p++) {
        const uint32_t* As = (p == 2) ? Alo : Ahi;
        const uint32_t* Bs = (p == 1) ? Blo : Bhi;
#pragma unroll
        for (int ks = 0; ks < 8; ks++) {
            int kw = ks * 8 + tg;  // word index of k0 + tg*2
            uint32_t a[4][4];
#pragma unroll
            for (int mt = 0; mt < 4; mt++) {
                int r0 = (mw + mt * 16 + g) * SAK;
                a[mt][0] = As[r0 + kw];
                a[mt][1] = As[r0 + 8 * SAK + kw];
                a[mt][2] = As[r0 + kw + 4];
                a[mt][3] = As[r0 + 8 * SAK + kw + 4];
            }
            uint32_t b[4][2];
#pragma unroll
            for (int nt = 0; nt < 4; nt++) {
                int n0 = (nw + nt * 8 + g) * SAK;
                b[nt][0] = Bs[n0 + kw];
                b[nt][1] = Bs[n0 + kw + 4];
            }
#pragma unroll
            for (int mt = 0; mt < 4; mt++)
#pragma unroll
                for (int nt = 0; nt < 4; nt++)
                    mma_bf16(c[mt][nt], a[mt][0], a[mt][1], a[mt][2], a[mt][3], b[nt][0],
                             b[nt][1]);
        }
    }
    __syncthreads();  // done reading staged tiles; reuse region as fp32 C tile

    // --- write fragments (+bias) to smem C tile ---
    float* Cs = (float*)sm;  // 128 x CSTRIDE floats = 67584 B < 2*ASZ
#pragma unroll
    for (int nt = 0; nt < 4; nt++) {
        int col = nw + nt * 8 + tg * 2;
        float bz0 = __ldg(&bias[col]);
        float bz1 = __ldg(&bias[col + 1]);
#pragma unroll
        for (int mt = 0; mt < 4; mt++) {
            int r0 = mw + mt * 16 + g;
            Cs[r0 * CSTRIDE + col] = c[mt][nt][0] + bz0;
            Cs[r0 * CSTRIDE + col + 1] = c[mt][nt][1] + bz1;
            Cs[(r0 + 8) * CSTRIDE + col] = c[mt][nt][2] + bz0;
            Cs[(r0 + 8) * CSTRIDE + col + 1] = c[mt][nt][3] + bz1;
        }
    }
    __syncthreads();

    if (MODE == 0 || MODE == 2) {
#pragma unroll
        for (int i = 0; i < 16; i++) {
            int idx = tid + i * 256;
            int m = idx >> 5;
            int c4 = (idx & 31) << 2;
            int gm = bm + m;
            if (gm < N_NODES) {
                float4 o;
                o.x = Cs[m * CSTRIDE + c4];
                o.y = Cs[m * CSTRIDE + c4 + 1];
                o.z = Cs[m * CSTRIDE + c4 + 2];
                o.w = Cs[m * CSTRIDE + c4 + 3];
                if (MODE == 0) {
                    o.x = fmaxf(o.x, 0.f);
                    o.y = fmaxf(o.y, 0.f);
                    o.z = fmaxf(o.z, 0.f);
                    o.w = fmaxf(o.w, 0.f);
                }
                float* dst = (MODE == 0) ? (g_z1 + (size_t)gm * 128 + c4)
                                         : (out + (size_t)gm * 128 + c4);
                *(float4*)dst = o;
            }
        }
    } else {
        // LayerNorm stats: 2 threads per row, 64 cols each
        float* red = (float*)(sm + OFF_RED);
        float* red2 = red + 256;
        {
            int r = tid >> 1;
            int h0 = (tid & 1) * 64;
            float s = 0.f, s2 = 0.f;
#pragma unroll 8
            for (int cc = 0; cc < 64; cc++) {
                float v = Cs[r * CSTRIDE + h0 + cc];
                s += v;
                s2 += v * v;
            }
            red[r * 2 + (tid & 1)] = s;
            red2[r * 2 + (tid & 1)] = s2;
        }
        __syncthreads();
        __shared__ float rmean[128], rrstd[128];
        if (tid < 128) {
            float S = red[tid * 2] + red[tid * 2 + 1];
            float S2 = red2[tid * 2] + red2[tid * 2 + 1];
            float mean = S * (1.0f / 128.0f);
            float var = S2 * (1.0f / 128.0f) - mean * mean;
            rmean[tid] = mean;
            rrstd[tid] = rsqrtf(var + LN_EPS);
        }
        __syncthreads();
#pragma unroll 4
        for (int i = 0; i < 64; i++) {
            int e = i * 256 + tid;
            int r = e >> 7;
            int cc = e & 127;
            int gm = bm + r;
            if (gm < N_NODES) {
                float v = Cs[r * CSTRIDE + cc];
                v = (v - rmean[r]) * rrstd[r] * __ldg(&lng[cc]) + __ldg(&lnb[cc]);
                float gl = gelu_exact(v);
                size_t gi = (size_t)gm * 128 + cc;
                float hn = gl + g_h[gi];
                g_h[gi] = hn;
                g_hsum[gi] += hn;
            }
        }
    }
}

// ================= init =================
__global__ void k_init(const float* __restrict__ x) {
    int i = blockIdx.x * blockDim.x + threadIdx.x;
    if (i < N_NODES * D) {
        g_h[i] = x[i];
        g_hsum[i] = 0.0f;
    }
}

__global__ void k_zero_deg() {
    int i = blockIdx.x * blockDim.x + threadIdx.x;
    if (i < N_NODES) g_deg[i] = 0;
}

// ================= CSR build (bucket by dst, store src) =================
__global__ void k_hist(const int* __restrict__ dst) {
    int e = blockIdx.x * blockDim.x + threadIdx.x;
    if (e < N_EDGES) atomicAdd(&g_deg[dst[e]], 1);
}

__global__ void k_scan_local() {
    __shared__ int s[1024];
    int i = blockIdx.x * 1024 + threadIdx.x;
    int v = (i < N_NODES) ? g_deg[i] : 0;
    s[threadIdx.x] = v;
    __syncthreads();
#pragma unroll
    for (int off = 1; off < 1024; off <<= 1) {
        int t = (threadIdx.x >= off) ? s[threadIdx.x - off] : 0;
        __syncthreads();
        s[threadIdx.x] += t;
        __syncthreads();
    }
    if (i < N_NODES) g_off[i] = s[threadIdx.x] - v;
    if (threadIdx.x == 1023) g_bsum[blockIdx.x] = s[1023];
}

__global__ void k_scan_top(int nblk) {
    if (threadIdx.x == 0 && blockIdx.x == 0) {
        int run = 0;
        for (int b = 0; b < nblk; b++) {
            int t = g_bsum[b];
            g_bsum[b] = run;
            run += t;
        }
    }
}

__global__ void k_scan_add() {
    int i = blockIdx.x * blockDim.x + threadIdx.x;
    if (i < N_NODES) {
        int o = g_off[i] + g_bsum[i >> 10];
        g_off[i] = o;
        g_cur[i] = o;
    }
}

__global__ void k_scatter(const int* __restrict__ src, const int* __restrict__ dst) {
    int e = blockIdx.x * blockDim.x + threadIdx.x;
    if (e < N_EDGES) {
        int d = dst[e];
        int p = atomicAdd(&g_cur[d], 1);
        g_col[p] = src[e];
    }
}

// ================= aggregation: warp per node, float4 lanes =================
__global__ __launch_bounds__(128) void k_agg(const float* __restrict__ eps, int layer) {
    int wid = threadIdx.x >> 5, lane = threadIdx.x & 31;
    int n = blockIdx.x * 4 + wid;
    if (n >= N_NODES) return;
    float e1 = 1.0f + __ldg(&eps[layer]);
    const float4* h4 = (const float4*)g_h;
    float4 acc = __ldg(&h4[(size_t)n * 32 + lane]);
    acc.x *= e1; acc.y *= e1; acc.z *= e1; acc.w *= e1;
    int beg = g_off[n], cnt = g_deg[n];
    for (int base = 0; base < cnt; base += 32) {
        int m = min(32, cnt - base);
        int id = (lane < m) ? g_col[beg + base + lane] : 0;
        int j = 0;
        for (; j + 4 <= m; j += 4) {
            int n0 = __shfl_sync(0xffffffffu, id, j);
            int n1 = __shfl_sync(0xffffffffu, id, j + 1);
            int n2 = __shfl_sync(0xffffffffu, id, j + 2);
            int n3 = __shfl_sync(0xffffffffu, id, j + 3);
            float4 a = __ldg(&h4[(size_t)n0 * 32 + lane]);
            float4 b = __ldg(&h4[(size_t)n1 * 32 + lane]);
            float4 c = __ldg(&h4[(size_t)n2 * 32 + lane]);
            float4 d = __ldg(&h4[(size_t)n3 * 32 + lane]);
            acc.x += a.x + b.x + c.x + d.x;
            acc.y += a.y + b.y + c.y + d.y;
            acc.z += a.z + b.z + c.z + d.z;
            acc.w += a.w + b.w + c.w + d.w;
        }
        for (; j < m; j++) {
            int nb = __shfl_sync(0xffffffffu, id, j);
            float4 a = __ldg(&h4[(size_t)nb * 32 + lane]);
            acc.x += a.x; acc.y += a.y; acc.z += a.z; acc.w += a.w;
        }
    }
    ((float4*)g_z)[(size_t)n * 32 + lane] = acc;
}

// ================= final LayerNorm of g_hsum -> g_z (warp per row) =================
__global__ __launch_bounds__(128) void k_rowln(const float* __restrict__ pg,
                                               const float* __restrict__ pb) {
    int wid = threadIdx.x >> 5, lane = threadIdx.x & 31;
    int r = blockIdx.x * 4 + wid;
    if (r >= N_NODES) return;
    float4 v = ((const float4*)g_hsum)[(size_t)r * 32 + lane];
    float s = v.x + v.y + v.z + v.w;
    float s2 = v.x * v.x + v.y * v.y + v.z * v.z + v.w * v.w;
#pragma unroll
    for (int o = 16; o > 0; o >>= 1) {
        s += __shfl_xor_sync(0xffffffffu, s, o);
        s2 += __shfl_xor_sync(0xffffffffu, s2, o);
    }
    float mean = s * (1.0f / 128.0f);
    float var = s2 * (1.0f / 128.0f) - mean * mean;
    float rstd = rsqrtf(var + LN_EPS);
    float4 g = __ldg(&((const float4*)pg)[lane]);
    float4 b = __ldg(&((const float4*)pb)[lane]);
    float4 o;
    o.x = (v.x - mean) * rstd * g.x + b.x;
    o.y = (v.y - mean) * rstd * g.y + b.y;
    o.z = (v.z - mean) * rstd * g.z + b.z;
    o.w = (v.w - mean) * rstd * g.w + b.w;
    ((float4*)g_z)[(size_t)r * 32 + lane] = o;
}

// ================= launch =================
extern "C" void kernel_launch(void* const* d_in, const int* in_sizes, int n_in,
                              void* d_out, int out_size) {
    const float* x = (const float*)d_in[0];
    const int* edge_index = (const int*)d_in[1];
    const float* W1 = (const float*)d_in[2];
    const float* b1 = (const float*)d_in[3];
    const float* W2 = (const float*)d_in[4];
    const float* b2 = (const float*)d_in[5];
    const float* eps = (const float*)d_in[6];
    const float* ln_g = (const float*)d_in[7];
    const float* ln_b = (const float*)d_in[8];
    const float* pln_g = (const float*)d_in[9];
    const float* pln_b = (const float*)d_in[10];
    const float* pW = (const float*)d_in[11];
    const float* pb = (const float*)d_in[12];
    float* out = (float*)d_out;

    const int* src = edge_index;
    const int* dst = edge_index + N_EDGES;

    cudaFuncSetAttribute(k_gemm_tc<0>, cudaFuncAttributeMaxDynamicSharedMemorySize, SMEM_TC);
    cudaFuncSetAttribute(k_gemm_tc<1>, cudaFuncAttributeMaxDynamicSharedMemorySize, SMEM_TC);
    cudaFuncSetAttribute(k_gemm_tc<2>, cudaFuncAttributeMaxDynamicSharedMemorySize, SMEM_TC);

    // init + CSR build
    k_init<<<(N_NODES * D + 255) / 256, 256>>>(x);
    k_zero_deg<<<(N_NODES + 255) / 256, 256>>>();
    k_hist<<<(N_EDGES + 255) / 256, 256>>>(dst);
    int nblk = (N_NODES + 1023) / 1024;
    k_scan_local<<<nblk, 1024>>>();
    k_scan_top<<<1, 32>>>(nblk);
    k_scan_add<<<(N_NODES + 255) / 256, 256>>>();
    k_scatter<<<(N_EDGES + 255) / 256, 256>>>(src, dst);

    int gblocks = (N_NODES + 127) / 128;  // 782
    int ablocks = (N_NODES + 3) / 4;      // 25000
    for (int i = 0; i < NLAYER; i++) {
        k_agg<<<ablocks, 128>>>(eps, i);
        k_gemm_tc<0><<<gblocks, 256, SMEM_TC>>>(W1 + (size_t)i * D * D, b1 + (size_t)i * D,
                                                nullptr, nullptr, nullptr);
        k_gemm_tc<1><<<gblocks, 256, SMEM_TC>>>(W2 + (size_t)i * D * D, b2 + (size_t)i * D,
                                                ln_g + (size_t)i * D, ln_b + (size_t)i * D,
                                                nullptr);
    }
    k_rowln<<<ablocks, 128>>>(pln_g, pln_b);
    k_gemm_tc<2><<<gblocks, 256, SMEM_TC>>>(pW, pb, nullptr, nullptr, out);
}

// round 7
// speedup vs baseline: 1.5067x; 1.5067x over previous
#include <cuda_runtime.h>
#include <cuda_bf16.h>
#include <cstdint>
#include <math.h>

#define N_NODES 100000
#define N_EDGES 1600000
#define D 128
#define NLAYER 3
#define LN_EPS 1e-5f
#define NBLK 98  // (N_NODES + 1023) / 1024

// ---------------- scratch (static __device__; referenced ONLY in device code) ----------------
__device__ float g_h[N_NODES * D];
__device__ float g_hsum[N_NODES * D];
__device__ float g_z[N_NODES * D];
__device__ float g_z1[N_NODES * D];
__device__ int g_deg[N_NODES];
__device__ int g_off[N_NODES];
__device__ int g_cur[N_NODES];
__device__ int g_col[N_EDGES];
__device__ int g_bsum[128];
// pre-split weights: 7 matrices (W1 x3, W2 x3, pW), transposed [n][k], bf16 pairs
__device__ uint32_t g_bhi[7 * 128 * 64];
__device__ uint32_t g_blo[7 * 128 * 64];

// ================= bf16 split helpers =================
__device__ __forceinline__ void split_bf16(float v, __nv_bfloat16& h, __nv_bfloat16& l) {
    h = __float2bfloat16(v);
    l = __float2bfloat16(v - __bfloat162float(h));
}
__device__ __forceinline__ uint32_t pack2(__nv_bfloat16 a, __nv_bfloat16 b) {
    return (uint32_t)__bfloat16_as_ushort(b) << 16 | (uint32_t)__bfloat16_as_ushort(a);
}
__device__ __forceinline__ float gelu_exact(float v) {
    return 0.5f * v * (1.0f + erff(v * 0.70710678118654752f));
}

// ================= smem layout for the GEMM =================
// A tiles row-major, 68-word rows (136 bf16) -> conflict-free fragment LDS
#define SAK 68
#define ASZ (128 * SAK * 4)          // 34816 bytes
#define OFF_AHI 0
#define OFF_ALO ASZ
#define OFF_RED (2 * ASZ)            // 69632: red[256]+red2[256]+rmean[128]+rrstd[128]
#define SMEM_TC (OFF_RED + 3072)     // 72704 bytes -> 2 CTAs/SM
#define CSTRIDE 132                  // fp32 C tile stride (reuses A region: 67584 <= 69632)

__device__ __forceinline__ void mma_bf16(float c[4], uint32_t a0, uint32_t a1, uint32_t a2,
                                         uint32_t a3, uint32_t b0, uint32_t b1) {
    asm volatile(
        "mma.sync.aligned.m16n8k16.row.col.f32.bf16.bf16.f32 "
        "{%0,%1,%2,%3}, {%4,%5,%6,%7}, {%8,%9}, {%0,%1,%2,%3};"
        : "+f"(c[0]), "+f"(c[1]), "+f"(c[2]), "+f"(c[3])
        : "r"(a0), "r"(a1), "r"(a2), "r"(a3), "r"(b0), "r"(b1));
}

// ================= pre-split weights kernel =================
__global__ void k_splitB(const float* __restrict__ W1, const float* __restrict__ W2,
                         const float* __restrict__ pW) {
    int i = blockIdx.x * blockDim.x + threadIdx.x;
    if (i >= 7 * 128 * 64) return;
    int mat = i >> 13;            // /8192
    int rem = i & 8191;
    int n = rem >> 6;             // output column (B row, transposed)
    int kw = rem & 63;            // k-pair index
    const float* Bw = (mat < 3) ? (W1 + (size_t)mat * 16384)
                                : ((mat < 6) ? (W2 + (size_t)(mat - 3) * 16384) : pW);
    float v0 = __ldg(&Bw[(size_t)(2 * kw) * 128 + n]);
    float v1 = __ldg(&Bw[(size_t)(2 * kw + 1) * 128 + n]);
    __nv_bfloat16 h0, l0, h1, l1;
    split_bf16(v0, h0, l0);
    split_bf16(v1, h1, l1);
    g_bhi[i] = pack2(h0, h1);
    g_blo[i] = pack2(l0, l1);
}

// ================= tensor-core GEMM (template on epilogue mode) =================
// MODE 0: g_z1 = relu(g_z @ W + b)
// MODE 1: ln+gelu+residual epilogue on (g_z1 @ W + b); updates g_h, g_hsum
// MODE 2: out = g_z @ W + b
template <int MODE>
__global__ void __launch_bounds__(256, 2)
k_gemm_tc(int mat, const float* __restrict__ bias, const float* __restrict__ lng,
          const float* __restrict__ lnb, float* __restrict__ out) {
    extern __shared__ char sm[];
    const int tid = threadIdx.x;
    const int wid = tid >> 5;
    const int lane = tid & 31;
    const int bm = blockIdx.x * 128;
    const float* A = (MODE == 1) ? g_z1 : g_z;

    uint32_t* Ahi = (uint32_t*)(sm + OFF_AHI);
    uint32_t* Alo = (uint32_t*)(sm + OFF_ALO);
    const uint32_t* BH = g_bhi + mat * 8192;
    const uint32_t* BL = g_blo + mat * 8192;

    // --- stage A (row-major M x K), split fp32 -> bf16 hi/lo ---
#pragma unroll
    for (int i = 0; i < 16; i++) {
        int idx = tid + i * 256;  // 0..4095 float4 units
        int m = idx >> 5;
        int c4 = (idx & 31) << 2;
        float4 v = make_float4(0.f, 0.f, 0.f, 0.f);
        int gm = bm + m;
        if (gm < N_NODES) v = *(const float4*)(A + (size_t)gm * 128 + c4);
        __nv_bfloat16 h0, h1, h2, h3, l0, l1, l2, l3;
        split_bf16(v.x, h0, l0);
        split_bf16(v.y, h1, l1);
        split_bf16(v.z, h2, l2);
        split_bf16(v.w, h3, l3);
        int w = m * SAK + (c4 >> 1);
        Ahi[w] = pack2(h0, h1);
        Ahi[w + 1] = pack2(h2, h3);
        Alo[w] = pack2(l0, l1);
        Alo[w + 1] = pack2(l2, l3);
    }
    __syncthreads();

    // --- MMA: warp covers rows mw..mw+63, cols nw..nw+31 ---
    const int g = lane >> 2, tg = lane & 3;
    const int mw = (wid & 1) * 64;
    const int nw = (wid >> 1) * 32;
    float c[4][4][4];
#pragma unroll
    for (int mt = 0; mt < 4; mt++)
#pragma unroll
        for (int nt = 0; nt < 4; nt++)
#pragma unroll
            for (int e = 0; e < 4; e++) c[mt][nt][e] = 0.f;

#pragma unroll
    for (int p = 0; p < 3; p++) {
        const uint32_t* As = (p == 2) ? Alo : Ahi;
        const uint32_t* Bg = (p == 1) ? BL : BH;
#pragma unroll
        for (int ks = 0; ks < 8; ks++) {
            int kw = ks * 8 + tg;
            uint32_t a[4][4];
#pragma unroll
            for (int mt = 0; mt < 4; mt++) {
                int r0 = (mw + mt * 16 + g) * SAK;
                a[mt][0] = As[r0 + kw];
                a[mt][1] = As[r0 + 8 * SAK + kw];
                a[mt][2] = As[r0 + kw + 4];
                a[mt][3] = As[r0 + 8 * SAK + kw + 4];
            }
            uint32_t b[4][2];
#pragma unroll
            for (int nt = 0; nt < 4; nt++) {
                int n0 = (nw + nt * 8 + g) << 6;
                b[nt][0] = __ldg(&Bg[n0 + kw]);
                b[nt][1] = __ldg(&Bg[n0 + kw + 4]);
            }
#pragma unroll
            for (int mt = 0; mt < 4; mt++)
#pragma unroll
                for (int nt = 0; nt < 4; nt++)
                    mma_bf16(c[mt][nt], a[mt][0], a[mt][1], a[mt][2], a[mt][3], b[nt][0],
                             b[nt][1]);
        }
    }
    __syncthreads();  // done reading staged A; reuse region as fp32 C tile

    // --- write fragments (+bias) to smem C tile ---
    float* Cs = (float*)sm;
#pragma unroll
    for (int nt = 0; nt < 4; nt++) {
        int col = nw + nt * 8 + tg * 2;
        float bz0 = __ldg(&bias[col]);
        float bz1 = __ldg(&bias[col + 1]);
#pragma unroll
        for (int mt = 0; mt < 4; mt++) {
            int r0 = mw + mt * 16 + g;
            Cs[r0 * CSTRIDE + col] = c[mt][nt][0] + bz0;
            Cs[r0 * CSTRIDE + col + 1] = c[mt][nt][1] + bz1;
            Cs[(r0 + 8) * CSTRIDE + col] = c[mt][nt][2] + bz0;
            Cs[(r0 + 8) * CSTRIDE + col + 1] = c[mt][nt][3] + bz1;
        }
    }
    __syncthreads();

    if (MODE == 0 || MODE == 2) {
#pragma unroll
        for (int i = 0; i < 16; i++) {
            int idx = tid + i * 256;
            int m = idx >> 5;
            int c4 = (idx & 31) << 2;
            int gm = bm + m;
            if (gm < N_NODES) {
                float4 o;
                o.x = Cs[m * CSTRIDE + c4];
                o.y = Cs[m * CSTRIDE + c4 + 1];
                o.z = Cs[m * CSTRIDE + c4 + 2];
                o.w = Cs[m * CSTRIDE + c4 + 3];
                if (MODE == 0) {
                    o.x = fmaxf(o.x, 0.f);
                    o.y = fmaxf(o.y, 0.f);
                    o.z = fmaxf(o.z, 0.f);
                    o.w = fmaxf(o.w, 0.f);
                }
                float* dst = (MODE == 0) ? (g_z1 + (size_t)gm * 128 + c4)
                                         : (out + (size_t)gm * 128 + c4);
                *(float4*)dst = o;
            }
        }
    } else {
        float* red = (float*)(sm + OFF_RED);
        float* red2 = red + 256;
        float* rmean = red2 + 256;
        float* rrstd = rmean + 128;
        {
            int r = tid >> 1;
            int h0 = (tid & 1) * 64;
            float s = 0.f, s2 = 0.f;
#pragma unroll 8
            for (int cc = 0; cc < 64; cc++) {
                float v = Cs[r * CSTRIDE + h0 + cc];
                s += v;
                s2 += v * v;
            }
            red[r * 2 + (tid & 1)] = s;
            red2[r * 2 + (tid & 1)] = s2;
        }
        __syncthreads();
        if (tid < 128) {
            float S = red[tid * 2] + red[tid * 2 + 1];
            float S2 = red2[tid * 2] + red2[tid * 2 + 1];
            float mean = S * (1.0f / 128.0f);
            float var = S2 * (1.0f / 128.0f) - mean * mean;
            rmean[tid] = mean;
            rrstd[tid] = rsqrtf(var + LN_EPS);
        }
        __syncthreads();
#pragma unroll 4
        for (int i = 0; i < 64; i++) {
            int e = i * 256 + tid;
            int r = e >> 7;
            int cc = e & 127;
            int gm = bm + r;
            if (gm < N_NODES) {
                float v = Cs[r * CSTRIDE + cc];
                v = (v - rmean[r]) * rrstd[r] * __ldg(&lng[cc]) + __ldg(&lnb[cc]);
                float gl = gelu_exact(v);
                size_t gi = (size_t)gm * 128 + cc;
                float hn = gl + g_h[gi];
                g_h[gi] = hn;
                g_hsum[gi] += hn;
            }
        }
    }
}

// ================= init (h, hsum, deg-zero fused) =================
__global__ void k_init(const float* __restrict__ x) {
    int i = blockIdx.x * blockDim.x + threadIdx.x;
    if (i < N_NODES * D) {
        g_h[i] = x[i];
        g_hsum[i] = 0.0f;
    }
    if (i < N_NODES) g_deg[i] = 0;
}

// ================= CSR build =================
__global__ void k_hist(const int* __restrict__ dst) {
    int e = blockIdx.x * blockDim.x + threadIdx.x;
    if (e < N_EDGES) atomicAdd(&g_deg[dst[e]], 1);
}

__global__ void k_scan_local() {
    __shared__ int s[1024];
    int i = blockIdx.x * 1024 + threadIdx.x;
    int v = (i < N_NODES) ? g_deg[i] : 0;
    s[threadIdx.x] = v;
    __syncthreads();
#pragma unroll
    for (int off = 1; off < 1024; off <<= 1) {
        int t = (threadIdx.x >= off) ? s[threadIdx.x - off] : 0;
        __syncthreads();
        s[threadIdx.x] += t;
        __syncthreads();
    }
    if (i < N_NODES) g_off[i] = s[threadIdx.x] - v;
    if (threadIdx.x == 1023) g_bsum[blockIdx.x] = s[1023];
}

// scan_top folded in: every block recomputes the 98-entry prefix in smem
__global__ void k_scan_addtop() {
    __shared__ int sp[NBLK + 1];
    __shared__ int sb[NBLK];
    if (threadIdx.x < NBLK) sb[threadIdx.x] = g_bsum[threadIdx.x];
    __syncthreads();
    if (threadIdx.x == 0) {
        int run = 0;
        for (int b = 0; b < NBLK; b++) {
            sp[b] = run;
            run += sb[b];
        }
    }
    __syncthreads();
    int i = blockIdx.x * blockDim.x + threadIdx.x;
    if (i < N_NODES) {
        int o = g_off[i] + sp[i >> 10];
        g_off[i] = o;
        g_cur[i] = o;
    }
}

__global__ void k_scatter(const int* __restrict__ src, const int* __restrict__ dst) {
    int e = blockIdx.x * blockDim.x + threadIdx.x;
    if (e < N_EDGES) {
        int d = dst[e];
        int p = atomicAdd(&g_cur[d], 1);
        g_col[p] = src[e];
    }
}

// ================= aggregation: warp per node, float4 lanes, MLP 8 =================
__global__ __launch_bounds__(128) void k_agg(const float* __restrict__ eps, int layer) {
    int wid = threadIdx.x >> 5, lane = threadIdx.x & 31;
    int n = blockIdx.x * 4 + wid;
    if (n >= N_NODES) return;
    float e1 = 1.0f + __ldg(&eps[layer]);
    const float4* h4 = (const float4*)g_h;
    float4 acc = __ldg(&h4[(size_t)n * 32 + lane]);
    acc.x *= e1; acc.y *= e1; acc.z *= e1; acc.w *= e1;
    int beg = g_off[n], cnt = g_deg[n];
    for (int base = 0; base < cnt; base += 32) {
        int m = min(32, cnt - base);
        int id = (lane < m) ? g_col[beg + base + lane] : 0;
        int j = 0;
        for (; j + 8 <= m; j += 8) {
            float4 t[8];
#pragma unroll
            for (int q = 0; q < 8; q++) {
                int nb = __shfl_sync(0xffffffffu, id, j + q);
                t[q] = __ldg(&h4[(size_t)nb * 32 + lane]);
            }
            acc.x += ((t[0].x + t[1].x) + (t[2].x + t[3].x)) +
                     ((t[4].x + t[5].x) + (t[6].x + t[7].x));
            acc.y += ((t[0].y + t[1].y) + (t[2].y + t[3].y)) +
                     ((t[4].y + t[5].y) + (t[6].y + t[7].y));
            acc.z += ((t[0].z + t[1].z) + (t[2].z + t[3].z)) +
                     ((t[4].z + t[5].z) + (t[6].z + t[7].z));
            acc.w += ((t[0].w + t[1].w) + (t[2].w + t[3].w)) +
                     ((t[4].w + t[5].w) + (t[6].w + t[7].w));
        }
        for (; j < m; j++) {
            int nb = __shfl_sync(0xffffffffu, id, j);
            float4 a = __ldg(&h4[(size_t)nb * 32 + lane]);
            acc.x += a.x; acc.y += a.y; acc.z += a.z; acc.w += a.w;
        }
    }
    ((float4*)g_z)[(size_t)n * 32 + lane] = acc;
}

// ================= final LayerNorm of g_hsum -> g_z (warp per row) =================
__global__ __launch_bounds__(128) void k_rowln(const float* __restrict__ pg,
                                               const float* __restrict__ pb) {
    int wid = threadIdx.x >> 5, lane = threadIdx.x & 31;
    int r = blockIdx.x * 4 + wid;
    if (r >= N_NODES) return;
    float4 v = ((const float4*)g_hsum)[(size_t)r * 32 + lane];
    float s = v.x + v.y + v.z + v.w;
    float s2 = v.x * v.x + v.y * v.y + v.z * v.z + v.w * v.w;
#pragma unroll
    for (int o = 16; o > 0; o >>= 1) {
        s += __shfl_xor_sync(0xffffffffu, s, o);
        s2 += __shfl_xor_sync(0xffffffffu, s2, o);
    }
    float mean = s * (1.0f / 128.0f);
    float var = s2 * (1.0f / 128.0f) - mean * mean;
    float rstd = rsqrtf(var + LN_EPS);
    float4 g = __ldg(&((const float4*)pg)[lane]);
    float4 b = __ldg(&((const float4*)pb)[lane]);
    float4 o;
    o.x = (v.x - mean) * rstd * g.x + b.x;
    o.y = (v.y - mean) * rstd * g.y + b.y;
    o.z = (v.z - mean) * rstd * g.z + b.z;
    o.w = (v.w - mean) * rstd * g.w + b.w;
    ((float4*)g_z)[(size_t)r * 32 + lane] = o;
}

// ================= launch =================
extern "C" void kernel_launch(void* const* d_in, const int* in_sizes, int n_in,
                              void* d_out, int out_size) {
    const float* x = (const float*)d_in[0];
    const int* edge_index = (const int*)d_in[1];
    const float* W1 = (const float*)d_in[2];
    const float* b1 = (const float*)d_in[3];
    const float* W2 = (const float*)d_in[4];
    const float* b2 = (const float*)d_in[5];
    const float* eps = (const float*)d_in[6];
    const float* ln_g = (const float*)d_in[7];
    const float* ln_b = (const float*)d_in[8];
    const float* pln_g = (const float*)d_in[9];
    const float* pln_b = (const float*)d_in[10];
    const float* pW = (const float*)d_in[11];
    const float* pb = (const float*)d_in[12];
    float* out = (float*)d_out;

    const int* src = edge_index;
    const int* dst = edge_index + N_EDGES;

    cudaFuncSetAttribute(k_gemm_tc<0>, cudaFuncAttributeMaxDynamicSharedMemorySize, SMEM_TC);
    cudaFuncSetAttribute(k_gemm_tc<1>, cudaFuncAttributeMaxDynamicSharedMemorySize, SMEM_TC);
    cudaFuncSetAttribute(k_gemm_tc<2>, cudaFuncAttributeMaxDynamicSharedMemorySize, SMEM_TC);

    // prologue
    k_init<<<(N_NODES * D + 255) / 256, 256>>>(x);
    k_hist<<<(N_EDGES + 255) / 256, 256>>>(dst);
    k_scan_local<<<NBLK, 1024>>>();
    k_scan_addtop<<<(N_NODES + 255) / 256, 256>>>();
    k_scatter<<<(N_EDGES + 255) / 256, 256>>>(src, dst);
    k_splitB<<<(7 * 128 * 64 + 255) / 256, 256>>>(W1, W2, pW);

    int gblocks = (N_NODES + 127) / 128;  // 782
    int ablocks = (N_NODES + 3) / 4;      // 25000
    for (int i = 0; i < NLAYER; i++) {
        k_agg<<<ablocks, 128>>>(eps, i);
        k_gemm_tc<0><<<gblocks, 256, SMEM_TC>>>(i, b1 + (size_t)i * D, nullptr, nullptr,
                                                nullptr);
        k_gemm_tc<1><<<gblocks, 256, SMEM_TC>>>(3 + i, b2 + (size_t)i * D,
                                                ln_g + (size_t)i * D, ln_b + (size_t)i * D,
                                                nullptr);
    }
    k_rowln<<<ablocks, 128>>>(pln_g, pln_b);
    k_gemm_tc<2><<<gblocks, 256, SMEM_TC>>>(6, pb, nullptr, nullptr, out);
}

// round 8
// speedup vs baseline: 2.0295x; 1.3469x over previous
#include <cuda_runtime.h>
#include <cuda_fp16.h>
#include <cstdint>
#include <math.h>

#define N_NODES 100000
#define N_EDGES 1600000
#define D 128
#define NLAYER 3
#define LN_EPS 1e-5f
#define NBLK 98  // (N_NODES + 1023) / 1024

// ---------------- scratch (static __device__; referenced ONLY in device code) ----------------
__device__ float g_h[N_NODES * D];       // residual stream (fp32)
__device__ float g_hsum[N_NODES * D];    // jumping-knowledge sum (fp32)
__device__ uint32_t g_zh[N_NODES * 64];  // z as packed half2 (GEMM A input)
__device__ uint32_t g_z1h[N_NODES * 64]; // z1 as packed half2 (GEMM A input)
__device__ int g_deg[N_NODES];
__device__ int g_off[N_NODES];
__device__ int g_cur[N_NODES];
__device__ int g_col[N_EDGES];
__device__ int g_bsum[128];
__device__ uint32_t g_bh[7 * 128 * 64];  // weights transposed [n][kpair], packed half2

// ================= helpers =================
__device__ __forceinline__ uint32_t packh2(float a, float b) {
    __half2 h = __floats2half2_rn(a, b);
    return *(uint32_t*)&h;
}
__device__ __forceinline__ float gelu_exact(float v) {
    return 0.5f * v * (1.0f + erff(v * 0.70710678118654752f));
}

// ================= smem layout for the GEMM =================
// A tile: 128 rows x 68 words (136 halves) -> conflict-free fragment LDS
#define SAK 68
#define OFF_RED 67584                 // after the fp32 C tile (128 x 132 x 4)
#define SMEM_TC (OFF_RED + 3072)      // 70656 bytes -> 2 CTAs/SM
#define CSTRIDE 132

__device__ __forceinline__ void mma_f16(float c[4], uint32_t a0, uint32_t a1, uint32_t a2,
                                        uint32_t a3, uint32_t b0, uint32_t b1) {
    asm volatile(
        "mma.sync.aligned.m16n8k16.row.col.f32.f16.f16.f32 "
        "{%0,%1,%2,%3}, {%4,%5,%6,%7}, {%8,%9}, {%0,%1,%2,%3};"
        : "+f"(c[0]), "+f"(c[1]), "+f"(c[2]), "+f"(c[3])
        : "r"(a0), "r"(a1), "r"(a2), "r"(a3), "r"(b0), "r"(b1));
}

// ================= fused prologue: init h/hsum, zero deg, convert weights =================
__global__ void k_pro(const float* __restrict__ x, const float* __restrict__ W1,
                      const float* __restrict__ W2, const float* __restrict__ pW) {
    int i = blockIdx.x * blockDim.x + threadIdx.x;
    if (i < N_NODES * D) {
        g_h[i] = x[i];
        g_hsum[i] = 0.0f;
    }
    if (i < N_NODES) g_deg[i] = 0;
    if (i < 7 * 128 * 64) {
        int mat = i >> 13;
        int rem = i & 8191;
        int n = rem >> 6;
        int kw = rem & 63;
        const float* Bw = (mat < 3) ? (W1 + (size_t)mat * 16384)
                                    : ((mat < 6) ? (W2 + (size_t)(mat - 3) * 16384) : pW);
        float v0 = __ldg(&Bw[(size_t)(2 * kw) * 128 + n]);
        float v1 = __ldg(&Bw[(size_t)(2 * kw + 1) * 128 + n]);
        g_bh[i] = packh2(v0, v1);
    }
}

// ================= CSR build =================
__global__ void k_hist(const int* __restrict__ dst) {
    int e = blockIdx.x * blockDim.x + threadIdx.x;
    if (e < N_EDGES) atomicAdd(&g_deg[dst[e]], 1);
}

__global__ void k_scan_local() {
    __shared__ int s[1024];
    int i = blockIdx.x * 1024 + threadIdx.x;
    int v = (i < N_NODES) ? g_deg[i] : 0;
    s[threadIdx.x] = v;
    __syncthreads();
#pragma unroll
    for (int off = 1; off < 1024; off <<= 1) {
        int t = (threadIdx.x >= off) ? s[threadIdx.x - off] : 0;
        __syncthreads();
        s[threadIdx.x] += t;
        __syncthreads();
    }
    if (i < N_NODES) g_off[i] = s[threadIdx.x] - v;
    if (threadIdx.x == 1023) g_bsum[blockIdx.x] = s[1023];
}

__global__ void k_scan_addtop() {
    __shared__ int sp[NBLK + 1];
    __shared__ int sb[NBLK];
    if (threadIdx.x < NBLK) sb[threadIdx.x] = g_bsum[threadIdx.x];
    __syncthreads();
    if (threadIdx.x == 0) {
        int run = 0;
        for (int b = 0; b < NBLK; b++) {
            sp[b] = run;
            run += sb[b];
        }
    }
    __syncthreads();
    int i = blockIdx.x * blockDim.x + threadIdx.x;
    if (i < N_NODES) {
        int o = g_off[i] + sp[i >> 10];
        g_off[i] = o;
        g_cur[i] = o;
    }
}

__global__ void k_scatter(const int* __restrict__ src, const int* __restrict__ dst) {
    int e = blockIdx.x * blockDim.x + threadIdx.x;
    if (e < N_EDGES) {
        int d = dst[e];
        int p = atomicAdd(&g_cur[d], 1);
        g_col[p] = src[e];
    }
}

// ================= aggregation: warp per node, float4 lanes, emits packed fp16 =================
__global__ __launch_bounds__(128) void k_agg(const float* __restrict__ eps, int layer) {
    int wid = threadIdx.x >> 5, lane = threadIdx.x & 31;
    int n = blockIdx.x * 4 + wid;
    if (n >= N_NODES) return;
    float e1 = 1.0f + __ldg(&eps[layer]);
    const float4* h4 = (const float4*)g_h;
    float4 acc = __ldg(&h4[(size_t)n * 32 + lane]);
    acc.x *= e1; acc.y *= e1; acc.z *= e1; acc.w *= e1;
    int beg = g_off[n], cnt = g_deg[n];
    for (int base = 0; base < cnt; base += 32) {
        int m = min(32, cnt - base);
        int id = (lane < m) ? g_col[beg + base + lane] : 0;
        int j = 0;
        for (; j + 8 <= m; j += 8) {
            float4 t[8];
#pragma unroll
            for (int q = 0; q < 8; q++) {
                int nb = __shfl_sync(0xffffffffu, id, j + q);
                t[q] = __ldg(&h4[(size_t)nb * 32 + lane]);
            }
            acc.x += ((t[0].x + t[1].x) + (t[2].x + t[3].x)) +
                     ((t[4].x + t[5].x) + (t[6].x + t[7].x));
            acc.y += ((t[0].y + t[1].y) + (t[2].y + t[3].y)) +
                     ((t[4].y + t[5].y) + (t[6].y + t[7].y));
            acc.z += ((t[0].z + t[1].z) + (t[2].z + t[3].z)) +
                     ((t[4].z + t[5].z) + (t[6].z + t[7].z));
            acc.w += ((t[0].w + t[1].w) + (t[2].w + t[3].w)) +
                     ((t[4].w + t[5].w) + (t[6].w + t[7].w));
        }
        for (; j < m; j++) {
            int nb = __shfl_sync(0xffffffffu, id, j);
            float4 a = __ldg(&h4[(size_t)nb * 32 + lane]);
            acc.x += a.x; acc.y += a.y; acc.z += a.z; acc.w += a.w;
        }
    }
    uint2 o = make_uint2(packh2(acc.x, acc.y), packh2(acc.z, acc.w));
    ((uint2*)g_zh)[(size_t)n * 32 + lane] = o;
}

// ================= GEMM (fp16 single-product, fused epilogues) =================
// MODE 0: g_z1h = pack16(relu(z @ W + b))
// MODE 1: ln+gelu+residual on (z1 @ W + b); updates g_h (fp32), g_hsum (fp32)
// MODE 2: out = z @ W + b (fp32)
template <int MODE>
__global__ void __launch_bounds__(256, 2)
k_gemm_tc(int mat, const float* __restrict__ bias, const float* __restrict__ lng,
          const float* __restrict__ lnb, float* __restrict__ out) {
    extern __shared__ char sm[];
    const int tid = threadIdx.x;
    const int wid = tid >> 5;
    const int lane = tid & 31;
    const int bm = blockIdx.x * 128;
    const uint32_t* Ag = (MODE == 1) ? g_z1h : g_zh;
    const uint32_t* Bg = g_bh + mat * 8192;
    uint32_t* As = (uint32_t*)sm;

    // --- stage A: pure copy of packed fp16 rows into 68-word-stride smem ---
#pragma unroll
    for (int i = 0; i < 8; i++) {
        int idx = tid + i * 256;  // uint4 units, 2048 total
        int m = idx >> 4;
        int wq = (idx & 15) << 2;
        uint4 v = make_uint4(0u, 0u, 0u, 0u);
        int gm = bm + m;
        if (gm < N_NODES) v = __ldg(&((const uint4*)Ag)[(size_t)gm * 16 + (wq >> 2)]);
        *(uint4*)&As[m * SAK + wq] = v;
    }
    __syncthreads();

    // --- MMA: warp covers rows mw..mw+63, cols nw..nw+31 ---
    const int g = lane >> 2, tg = lane & 3;
    const int mw = (wid & 1) * 64;
    const int nw = (wid >> 1) * 32;
    float c[4][4][4];
#pragma unroll
    for (int mt = 0; mt < 4; mt++)
#pragma unroll
        for (int nt = 0; nt < 4; nt++)
#pragma unroll
            for (int e = 0; e < 4; e++) c[mt][nt][e] = 0.f;

#pragma unroll
    for (int ks = 0; ks < 8; ks++) {
        int kw = ks * 8 + tg;
        uint32_t a[4][4];
#pragma unroll
        for (int mt = 0; mt < 4; mt++) {
            int r0 = (mw + mt * 16 + g) * SAK;
            a[mt][0] = As[r0 + kw];
            a[mt][1] = As[r0 + 8 * SAK + kw];
            a[mt][2] = As[r0 + kw + 4];
            a[mt][3] = As[r0 + 8 * SAK + kw + 4];
        }
        uint32_t b[4][2];
#pragma unroll
        for (int nt = 0; nt < 4; nt++) {
            int n0 = (nw + nt * 8 + g) << 6;
            b[nt][0] = __ldg(&Bg[n0 + kw]);
            b[nt][1] = __ldg(&Bg[n0 + kw + 4]);
        }
#pragma unroll
        for (int mt = 0; mt < 4; mt++)
#pragma unroll
            for (int nt = 0; nt < 4; nt++)
                mma_f16(c[mt][nt], a[mt][0], a[mt][1], a[mt][2], a[mt][3], b[nt][0], b[nt][1]);
    }
    __syncthreads();  // done reading staged A; reuse smem as fp32 C tile

    // --- write fragments (+bias) to smem C tile ---
    float* Cs = (float*)sm;
#pragma unroll
    for (int nt = 0; nt < 4; nt++) {
        int col = nw + nt * 8 + tg * 2;
        float bz0 = __ldg(&bias[col]);
        float bz1 = __ldg(&bias[col + 1]);
#pragma unroll
        for (int mt = 0; mt < 4; mt++) {
            int r0 = mw + mt * 16 + g;
            Cs[r0 * CSTRIDE + col] = c[mt][nt][0] + bz0;
            Cs[r0 * CSTRIDE + col + 1] = c[mt][nt][1] + bz1;
            Cs[(r0 + 8) * CSTRIDE + col] = c[mt][nt][2] + bz0;
            Cs[(r0 + 8) * CSTRIDE + col + 1] = c[mt][nt][3] + bz1;
        }
    }
    __syncthreads();

    if (MODE == 0) {
        // relu + pack fp16 pairs, coalesced uint2 stores
#pragma unroll
        for (int i = 0; i < 16; i++) {
            int idx = tid + i * 256;  // uint2 units, 4096 total
            int m = idx >> 5;
            int u = idx & 31;  // 4 cols starting at 4u
            int gm = bm + m;
            if (gm < N_NODES) {
                float v0 = fmaxf(Cs[m * CSTRIDE + 4 * u], 0.f);
                float v1 = fmaxf(Cs[m * CSTRIDE + 4 * u + 1], 0.f);
                float v2 = fmaxf(Cs[m * CSTRIDE + 4 * u + 2], 0.f);
                float v3 = fmaxf(Cs[m * CSTRIDE + 4 * u + 3], 0.f);
                ((uint2*)g_z1h)[(size_t)gm * 32 + u] = make_uint2(packh2(v0, v1), packh2(v2, v3));
            }
        }
    } else if (MODE == 2) {
#pragma unroll
        for (int i = 0; i < 16; i++) {
            int idx = tid + i * 256;
            int m = idx >> 5;
            int c4 = (idx & 31) << 2;
            int gm = bm + m;
            if (gm < N_NODES) {
                float4 o;
                o.x = Cs[m * CSTRIDE + c4];
                o.y = Cs[m * CSTRIDE + c4 + 1];
                o.z = Cs[m * CSTRIDE + c4 + 2];
                o.w = Cs[m * CSTRIDE + c4 + 3];
                *(float4*)(out + (size_t)gm * 128 + c4) = o;
            }
        }
    } else {
        float* red = (float*)(sm + OFF_RED);
        float* red2 = red + 256;
        float* rmean = red2 + 256;
        float* rrstd = rmean + 128;
        {
            int r = tid >> 1;
            int h0 = (tid & 1) * 64;
            float s = 0.f, s2 = 0.f;
#pragma unroll 8
            for (int cc = 0; cc < 64; cc++) {
                float v = Cs[r * CSTRIDE + h0 + cc];
                s += v;
                s2 += v * v;
            }
            red[r * 2 + (tid & 1)] = s;
            red2[r * 2 + (tid & 1)] = s2;
        }
        __syncthreads();
        if (tid < 128) {
            float S = red[tid * 2] + red[tid * 2 + 1];
            float S2 = red2[tid * 2] + red2[tid * 2 + 1];
            float mean = S * (1.0f / 128.0f);
            float var = S2 * (1.0f / 128.0f) - mean * mean;
            rmean[tid] = mean;
            rrstd[tid] = rsqrtf(var + LN_EPS);
        }
        __syncthreads();
#pragma unroll 4
        for (int i = 0; i < 64; i++) {
            int e = i * 256 + tid;
            int r = e >> 7;
            int cc = e & 127;
            int gm = bm + r;
            if (gm < N_NODES) {
                float v = Cs[r * CSTRIDE + cc];
                v = (v - rmean[r]) * rrstd[r] * __ldg(&lng[cc]) + __ldg(&lnb[cc]);
                float gl = gelu_exact(v);
                size_t gi = (size_t)gm * 128 + cc;
                float hn = gl + g_h[gi];
                g_h[gi] = hn;
                g_hsum[gi] += hn;
            }
        }
    }
}

// ================= final LayerNorm of g_hsum -> g_zh (warp per row, packed fp16) =================
__global__ __launch_bounds__(128) void k_rowln(const float* __restrict__ pg,
                                               const float* __restrict__ pb) {
    int wid = threadIdx.x >> 5, lane = threadIdx.x & 31;
    int r = blockIdx.x * 4 + wid;
    if (r >= N_NODES) return;
    float4 v = ((const float4*)g_hsum)[(size_t)r * 32 + lane];
    float s = v.x + v.y + v.z + v.w;
    float s2 = v.x * v.x + v.y * v.y + v.z * v.z + v.w * v.w;
#pragma unroll
    for (int o = 16; o > 0; o >>= 1) {
        s += __shfl_xor_sync(0xffffffffu, s, o);
        s2 += __shfl_xor_sync(0xffffffffu, s2, o);
    }
    float mean = s * (1.0f / 128.0f);
    float var = s2 * (1.0f / 128.0f) - mean * mean;
    float rstd = rsqrtf(var + LN_EPS);
    float4 g = __ldg(&((const float4*)pg)[lane]);
    float4 b = __ldg(&((const float4*)pb)[lane]);
    float o0 = (v.x - mean) * rstd * g.x + b.x;
    float o1 = (v.y - mean) * rstd * g.y + b.y;
    float o2 = (v.z - mean) * rstd * g.z + b.z;
    float o3 = (v.w - mean) * rstd * g.w + b.w;
    ((uint2*)g_zh)[(size_t)r * 32 + lane] = make_uint2(packh2(o0, o1), packh2(o2, o3));
}

// ================= launch =================
extern "C" void kernel_launch(void* const* d_in, const int* in_sizes, int n_in,
                              void* d_out, int out_size) {
    const float* x = (const float*)d_in[0];
    const int* edge_index = (const int*)d_in[1];
    const float* W1 = (const float*)d_in[2];
    const float* b1 = (const float*)d_in[3];
    const float* W2 = (const float*)d_in[4];
    const float* b2 = (const float*)d_in[5];
    const float* eps = (const float*)d_in[6];
    const float* ln_g = (const float*)d_in[7];
    const float* ln_b = (const float*)d_in[8];
    const float* pln_g = (const float*)d_in[9];
    const float* pln_b = (const float*)d_in[10];
    const float* pW = (const float*)d_in[11];
    const float* pb = (const float*)d_in[12];
    float* out = (float*)d_out;

    const int* src = edge_index;
    const int* dst = edge_index + N_EDGES;

    cudaFuncSetAttribute(k_gemm_tc<0>, cudaFuncAttributeMaxDynamicSharedMemorySize, SMEM_TC);
    cudaFuncSetAttribute(k_gemm_tc<1>, cudaFuncAttributeMaxDynamicSharedMemorySize, SMEM_TC);
    cudaFuncSetAttribute(k_gemm_tc<2>, cudaFuncAttributeMaxDynamicSharedMemorySize, SMEM_TC);

    // prologue (fused) + CSR build
    k_pro<<<(N_NODES * D + 255) / 256, 256>>>(x, W1, W2, pW);
    k_hist<<<(N_EDGES + 255) / 256, 256>>>(dst);
    k_scan_local<<<NBLK, 1024>>>();
    k_scan_addtop<<<(N_NODES + 255) / 256, 256>>>();
    k_scatter<<<(N_EDGES + 255) / 256, 256>>>(src, dst);

    int gblocks = (N_NODES + 127) / 128;  // 782
    int ablocks = (N_NODES + 3) / 4;      // 25000
    for (int i = 0; i < NLAYER; i++) {
        k_agg<<<ablocks, 128>>>(eps, i);
        k_gemm_tc<0><<<gblocks, 256, SMEM_TC>>>(i, b1 + (size_t)i * D, nullptr, nullptr,
                                                nullptr);
        k_gemm_tc<1><<<gblocks, 256, SMEM_TC>>>(3 + i, b2 + (size_t)i * D,
                                                ln_g + (size_t)i * D, ln_b + (size_t)i * D,
                                                nullptr);
    }
    k_rowln<<<ablocks, 128>>>(pln_g, pln_b);
    k_gemm_tc<2><<<gblocks, 256, SMEM_TC>>>(6, pb, nullptr, nullptr, out);
}

// round 10
// speedup vs baseline: 2.2233x; 1.0955x over previous
#include <cuda_runtime.h>
#include <cuda_fp16.h>
#include <cstdint>
#include <math.h>

#define N_NODES 100000
#define N_EDGES 1600000
#define D 128
#define NLAYER 3
#define LN_EPS 1e-5f
#define NBLK 98  // (N_NODES + 1023) / 1024

// ---------------- scratch (static __device__; referenced ONLY in device code) ----------------
__device__ float g_h[N_NODES * D];       // residual stream (fp32)
__device__ float g_hsum[N_NODES * D];    // jumping-knowledge sum (fp32)
__device__ uint32_t g_zh[N_NODES * 64];  // z as packed half2 (GEMM A input)
__device__ int g_deg[N_NODES];
__device__ int g_off[N_NODES];
__device__ int g_cur[N_NODES];
__device__ int g_col[N_EDGES];
__device__ int g_bsum[128];
__device__ uint32_t g_bh[7 * 128 * 64];  // weights transposed [n][kpair], packed half2

// ================= helpers =================
__device__ __forceinline__ uint32_t packh2(float a, float b) {
    __half2 h = __floats2half2_rn(a, b);
    return *(uint32_t*)&h;
}
__device__ __forceinline__ float gelu_exact(float v) {
    return 0.5f * v * (1.0f + erff(v * 0.70710678118654752f));
}

// ================= smem layout =================
// A tile: 128 rows x 68 words (136 halves) -> conflict-free fragment LDS
#define SAK 68
#define OFF_RED 67584                 // after the fp32 C tile (128 x 132 x 4)
#define SMEM_TC (OFF_RED + 3072)      // 70656 bytes -> 2 CTAs/SM
#define OFF_REDF 34816                // k_final: red arrays right after A tile
#define CSTRIDE 132

__device__ __forceinline__ void mma_f16(float c[4], uint32_t a0, uint32_t a1, uint32_t a2,
                                        uint32_t a3, uint32_t b0, uint32_t b1) {
    asm volatile(
        "mma.sync.aligned.m16n8k16.row.col.f32.f16.f16.f32 "
        "{%0,%1,%2,%3}, {%4,%5,%6,%7}, {%8,%9}, {%0,%1,%2,%3};"
        : "+f"(c[0]), "+f"(c[1]), "+f"(c[2]), "+f"(c[3])
        : "r"(a0), "r"(a1), "r"(a2), "r"(a3), "r"(b0), "r"(b1));
}

// run 8 k-steps of 128x128 MMA from smem A (SAK stride) + global B
__device__ __forceinline__ void mma_tile(const uint32_t* As, const uint32_t* Bg, int mw,
                                         int nw, int g, int tg, float c[4][4][4]) {
#pragma unroll
    for (int mt = 0; mt < 4; mt++)
#pragma unroll
        for (int nt = 0; nt < 4; nt++)
#pragma unroll
            for (int e = 0; e < 4; e++) c[mt][nt][e] = 0.f;
#pragma unroll
    for (int ks = 0; ks < 8; ks++) {
        int kw = ks * 8 + tg;
        uint32_t a[4][4];
#pragma unroll
        for (int mt = 0; mt < 4; mt++) {
            int r0 = (mw + mt * 16 + g) * SAK;
            a[mt][0] = As[r0 + kw];
            a[mt][1] = As[r0 + 8 * SAK + kw];
            a[mt][2] = As[r0 + kw + 4];
            a[mt][3] = As[r0 + 8 * SAK + kw + 4];
        }
        uint32_t b[4][2];
#pragma unroll
        for (int nt = 0; nt < 4; nt++) {
            int n0 = (nw + nt * 8 + g) << 6;
            b[nt][0] = __ldg(&Bg[n0 + kw]);
            b[nt][1] = __ldg(&Bg[n0 + kw + 4]);
        }
#pragma unroll
        for (int mt = 0; mt < 4; mt++)
#pragma unroll
            for (int nt = 0; nt < 4; nt++)
                mma_f16(c[mt][nt], a[mt][0], a[mt][1], a[mt][2], a[mt][3], b[nt][0], b[nt][1]);
    }
}

// ================= fused prologue: init h/hsum, zero deg, convert weights =================
__global__ void k_pro(const float* __restrict__ x, const float* __restrict__ W1,
                      const float* __restrict__ W2, const float* __restrict__ pW) {
    int i = blockIdx.x * blockDim.x + threadIdx.x;
    if (i < N_NODES * D) {
        g_h[i] = x[i];
        g_hsum[i] = 0.0f;
    }
    if (i < N_NODES) g_deg[i] = 0;
    if (i < 7 * 128 * 64) {
        int mat = i >> 13;
        int rem = i & 8191;
        int n = rem >> 6;
        int kw = rem & 63;
        const float* Bw = (mat < 3) ? (W1 + (size_t)mat * 16384)
                                    : ((mat < 6) ? (W2 + (size_t)(mat - 3) * 16384) : pW);
        float v0 = __ldg(&Bw[(size_t)(2 * kw) * 128 + n]);
        float v1 = __ldg(&Bw[(size_t)(2 * kw + 1) * 128 + n]);
        g_bh[i] = packh2(v0, v1);
    }
}

// ================= CSR build =================
__global__ void k_hist(const int* __restrict__ dst) {
    int e = blockIdx.x * blockDim.x + threadIdx.x;
    if (e < N_EDGES) atomicAdd(&g_deg[dst[e]], 1);
}

__global__ void k_scan_local() {
    __shared__ int s[1024];
    int i = blockIdx.x * 1024 + threadIdx.x;
    int v = (i < N_NODES) ? g_deg[i] : 0;
    s[threadIdx.x] = v;
    __syncthreads();
#pragma unroll
    for (int off = 1; off < 1024; off <<= 1) {
        int t = (threadIdx.x >= off) ? s[threadIdx.x - off] : 0;
        __syncthreads();
        s[threadIdx.x] += t;
        __syncthreads();
    }
    if (i < N_NODES) g_off[i] = s[threadIdx.x] - v;
    if (threadIdx.x == 1023) g_bsum[blockIdx.x] = s[1023];
}

__global__ void k_scan_addtop() {
    __shared__ int sp[NBLK + 1];
    __shared__ int sb[NBLK];
    if (threadIdx.x < NBLK) sb[threadIdx.x] = g_bsum[threadIdx.x];
    __syncthreads();
    if (threadIdx.x == 0) {
        int run = 0;
        for (int b = 0; b < NBLK; b++) {
            sp[b] = run;
            run += sb[b];
        }
    }
    __syncthreads();
    int i = blockIdx.x * blockDim.x + threadIdx.x;
    if (i < N_NODES) {
        int o = g_off[i] + sp[i >> 10];
        g_off[i] = o;
        g_cur[i] = o;
    }
}

__global__ void k_scatter(const int* __restrict__ src, const int* __restrict__ dst) {
    int e = blockIdx.x * blockDim.x + threadIdx.x;
    if (e < N_EDGES) {
        int d = dst[e];
        int p = atomicAdd(&g_cur[d], 1);
        g_col[p] = src[e];
    }
}

// ================= aggregation: warp per node, float4 lanes, emits packed fp16 =================
__global__ __launch_bounds__(128) void k_agg(const float* __restrict__ eps, int layer) {
    int wid = threadIdx.x >> 5, lane = threadIdx.x & 31;
    int n = blockIdx.x * 4 + wid;
    if (n >= N_NODES) return;
    float e1 = 1.0f + __ldg(&eps[layer]);
    const float4* h4 = (const float4*)g_h;
    float4 acc = __ldg(&h4[(size_t)n * 32 + lane]);
    acc.x *= e1; acc.y *= e1; acc.z *= e1; acc.w *= e1;
    int beg = g_off[n], cnt = g_deg[n];
    for (int base = 0; base < cnt; base += 32) {
        int m = min(32, cnt - base);
        int id = (lane < m) ? g_col[beg + base + lane] : 0;
        int j = 0;
        for (; j + 8 <= m; j += 8) {
            float4 t[8];
#pragma unroll
            for (int q = 0; q < 8; q++) {
                int nb = __shfl_sync(0xffffffffu, id, j + q);
                t[q] = __ldg(&h4[(size_t)nb * 32 + lane]);
            }
            acc.x += ((t[0].x + t[1].x) + (t[2].x + t[3].x)) +
                     ((t[4].x + t[5].x) + (t[6].x + t[7].x));
            acc.y += ((t[0].y + t[1].y) + (t[2].y + t[3].y)) +
                     ((t[4].y + t[5].y) + (t[6].y + t[7].y));
            acc.z += ((t[0].z + t[1].z) + (t[2].z + t[3].z)) +
                     ((t[4].z + t[5].z) + (t[6].z + t[7].z));
            acc.w += ((t[0].w + t[1].w) + (t[2].w + t[3].w)) +
                     ((t[4].w + t[5].w) + (t[6].w + t[7].w));
        }
        for (; j < m; j++) {
            int nb = __shfl_sync(0xffffffffu, id, j);
            float4 a = __ldg(&h4[(size_t)nb * 32 + lane]);
            acc.x += a.x; acc.y += a.y; acc.z += a.z; acc.w += a.w;
        }
    }
    uint2 o = make_uint2(packh2(acc.x, acc.y), packh2(acc.z, acc.w));
    ((uint2*)g_zh)[(size_t)n * 32 + lane] = o;
}

// ================= fused per-layer MLP =================
// z1 = relu(z @ W1 + b1) stays in smem (fp16), then z2 = z1 @ W2 + b2,
// then LN + GELU + residual -> g_h, g_hsum.
__global__ void __launch_bounds__(256, 2)
k_mlp(int li, const float* __restrict__ b1, const float* __restrict__ b2,
      const float* __restrict__ lng, const float* __restrict__ lnb) {
    extern __shared__ char sm[];
    const int tid = threadIdx.x;
    const int wid = tid >> 5;
    const int lane = tid & 31;
    const int bm = blockIdx.x * 128;
    uint32_t* As = (uint32_t*)sm;

    // --- stage z tile (packed fp16 copy) ---
#pragma unroll
    for (int i = 0; i < 8; i++) {
        int idx = tid + i * 256;  // uint4 units, 2048 total
        int m = idx >> 4;
        int wq = (idx & 15) << 2;
        uint4 v = make_uint4(0u, 0u, 0u, 0u);
        int gm = bm + m;
        if (gm < N_NODES) v = __ldg(&((const uint4*)g_zh)[(size_t)gm * 16 + (wq >> 2)]);
        *(uint4*)&As[m * SAK + wq] = v;
    }
    __syncthreads();

    const int g = lane >> 2, tg = lane & 3;
    const int mw = (wid & 1) * 64;
    const int nw = (wid >> 1) * 32;
    float c[4][4][4];

    // --- GEMM1: z @ W1 ---
    mma_tile(As, g_bh + li * 8192, mw, nw, g, tg, c);
    __syncthreads();  // all A reads done before overwrite

    // --- relu(z1 + b1) -> As (fp16, in place) ---
#pragma unroll
    for (int nt = 0; nt < 4; nt++) {
        int col = nw + nt * 8 + tg * 2;
        float bz0 = __ldg(&b1[col]);
        float bz1 = __ldg(&b1[col + 1]);
        int wc = (col >> 1);  // word column
#pragma unroll
        for (int mt = 0; mt < 4; mt++) {
            int r0 = mw + mt * 16 + g;
            As[r0 * SAK + wc] =
                packh2(fmaxf(c[mt][nt][0] + bz0, 0.f), fmaxf(c[mt][nt][1] + bz1, 0.f));
            As[(r0 + 8) * SAK + wc] =
                packh2(fmaxf(c[mt][nt][2] + bz0, 0.f), fmaxf(c[mt][nt][3] + bz1, 0.f));
        }
    }
    __syncthreads();

    // --- GEMM2: z1 @ W2 ---
    mma_tile(As, g_bh + (3 + li) * 8192, mw, nw, g, tg, c);
    __syncthreads();  // A reads done; reuse smem as fp32 C tile

    // --- write fragments (+b2) to smem C tile ---
    float* Cs = (float*)sm;
#pragma unroll
    for (int nt = 0; nt < 4; nt++) {
        int col = nw + nt * 8 + tg * 2;
        float bz0 = __ldg(&b2[col]);
        float bz1 = __ldg(&b2[col + 1]);
#pragma unroll
        for (int mt = 0; mt < 4; mt++) {
            int r0 = mw + mt * 16 + g;
            Cs[r0 * CSTRIDE + col] = c[mt][nt][0] + bz0;
            Cs[r0 * CSTRIDE + col + 1] = c[mt][nt][1] + bz1;
            Cs[(r0 + 8) * CSTRIDE + col] = c[mt][nt][2] + bz0;
            Cs[(r0 + 8) * CSTRIDE + col + 1] = c[mt][nt][3] + bz1;
        }
    }
    __syncthreads();

    // --- LN + GELU + residual + hsum ---
    float* red = (float*)(sm + OFF_RED);
    float* red2 = red + 256;
    float* rmean = red2 + 256;
    float* rrstd = rmean + 128;
    {
        int r = tid >> 1;
        int h0 = (tid & 1) * 64;
        float s = 0.f, s2 = 0.f;
#pragma unroll 8
        for (int cc = 0; cc < 64; cc++) {
            float v = Cs[r * CSTRIDE + h0 + cc];
            s += v;
            s2 += v * v;
        }
        red[r * 2 + (tid & 1)] = s;
        red2[r * 2 + (tid & 1)] = s2;
    }
    __syncthreads();
    if (tid < 128) {
        float S = red[tid * 2] + red[tid * 2 + 1];
        float S2 = red2[tid * 2] + red2[tid * 2 + 1];
        float mean = S * (1.0f / 128.0f);
        float var = S2 * (1.0f / 128.0f) - mean * mean;
        rmean[tid] = mean;
        rrstd[tid] = rsqrtf(var + LN_EPS);
    }
    __syncthreads();
#pragma unroll 4
    for (int i = 0; i < 64; i++) {
        int e = i * 256 + tid;
        int r = e >> 7;
        int cc = e & 127;
        int gm = bm + r;
        if (gm < N_NODES) {
            float v = Cs[r * CSTRIDE + cc];
            v = (v - rmean[r]) * rrstd[r] * __ldg(&lng[cc]) + __ldg(&lnb[cc]);
            float gl = gelu_exact(v);
            size_t gi = (size_t)gm * 128 + cc;
            float hn = gl + g_h[gi];
            g_h[gi] = hn;
            g_hsum[gi] += hn;
        }
    }
}

// ================= fused final: row-LN(hsum) @ pW + pb -> out =================
__global__ void __launch_bounds__(256, 2)
k_final(const float* __restrict__ pg, const float* __restrict__ pbln,
        const float* __restrict__ pbias, float* __restrict__ out) {
    extern __shared__ char sm[];
    const int tid = threadIdx.x;
    const int wid = tid >> 5;
    const int lane = tid & 31;
    const int bm = blockIdx.x * 128;
    uint32_t* As = (uint32_t*)sm;
    float* red = (float*)(sm + OFF_REDF);
    float* red2 = red + 256;
    float* rmean = red2 + 256;
    float* rrstd = rmean + 128;

    // --- LN stats from global hsum (L1-cached) ---
    {
        int r = tid >> 1;
        int h0 = (tid & 1) * 64;
        int gm = bm + r;
        float s = 0.f, s2 = 0.f;
        if (gm < N_NODES) {
#pragma unroll
            for (int cc = 0; cc < 64; cc += 4) {
                float4 v = *(const float4*)(g_hsum + (size_t)gm * 128 + h0 + cc);
                s += (v.x + v.y) + (v.z + v.w);
                s2 += (v.x * v.x + v.y * v.y) + (v.z * v.z + v.w * v.w);
            }
        }
        red[r * 2 + (tid & 1)] = s;
        red2[r * 2 + (tid & 1)] = s2;
    }
    __syncthreads();
    if (tid < 128) {
        float S = red[tid * 2] + red[tid * 2 + 1];
        float S2 = red2[tid * 2] + red2[tid * 2 + 1];
        float mean = S * (1.0f / 128.0f);
        float var = S2 * (1.0f / 128.0f) - mean * mean;
        rmean[tid] = mean;
        rrstd[tid] = rsqrtf(var + LN_EPS);
    }
    __syncthreads();

    // --- normalize + pack fp16 into A tile ---
#pragma unroll
    for (int i = 0; i < 16; i++) {
        int idx = tid + i * 256;  // 0..4095, 4 cols each
        int m = idx >> 5;
        int u = idx & 31;
        int gm = bm + m;
        float4 v = make_float4(0.f, 0.f, 0.f, 0.f);
        if (gm < N_NODES) v = *(const float4*)(g_hsum + (size_t)gm * 128 + 4 * u);
        float mean = rmean[m], rs = rrstd[m];
        float4 g4 = __ldg(&((const float4*)pg)[u]);
        float4 b4 = __ldg(&((const float4*)pbln)[u]);
        float o0 = (v.x - mean) * rs * g4.x + b4.x;
        float o1 = (v.y - mean) * rs * g4.y + b4.y;
        float o2 = (v.z - mean) * rs * g4.z + b4.z;
        float o3 = (v.w - mean) * rs * g4.w + b4.w;
        *(uint2*)&As[m * SAK + 2 * u] = make_uint2(packh2(o0, o1), packh2(o2, o3));
    }
    __syncthreads();

    const int g = lane >> 2, tg = lane & 3;
    const int mw = (wid & 1) * 64;
    const int nw = (wid >> 1) * 32;
    float c[4][4][4];
    mma_tile(As, g_bh + 6 * 8192, mw, nw, g, tg, c);
    __syncthreads();

    // --- write fragments (+pbias) to smem, then coalesced out stores ---
    float* Cs = (float*)sm;
#pragma unroll
    for (int nt = 0; nt < 4; nt++) {
        int col = nw + nt * 8 + tg * 2;
        float bz0 = __ldg(&pbias[col]);
        float bz1 = __ldg(&pbias[col + 1]);
#pragma unroll
        for (int mt = 0; mt < 4; mt++) {
            int r0 = mw + mt * 16 + g;
            Cs[r0 * CSTRIDE + col] = c[mt][nt][0] + bz0;
            Cs[r0 * CSTRIDE + col + 1] = c[mt][nt][1] + bz1;
            Cs[(r0 + 8) * CSTRIDE + col] = c[mt][nt][2] + bz0;
            Cs[(r0 + 8) * CSTRIDE + col + 1] = c[mt][nt][3] + bz1;
        }
    }
    __syncthreads();
#pragma unroll
    for (int i = 0; i < 16; i++) {
        int idx = tid + i * 256;
        int m = idx >> 5;
        int c4 = (idx & 31) << 2;
        int gm = bm + m;
        if (gm < N_NODES) {
            float4 o;
            o.x = Cs[m * CSTRIDE + c4];
            o.y = Cs[m * CSTRIDE + c4 + 1];
            o.z = Cs[m * CSTRIDE + c4 + 2];
            o.w = Cs[m * CSTRIDE + c4 + 3];
            *(float4*)(out + (size_t)gm * 128 + c4) = o;
        }
    }
}

// ================= launch =================
extern "C" void kernel_launch(void* const* d_in, const int* in_sizes, int n_in,
                              void* d_out, int out_size) {
    const float* x = (const float*)d_in[0];
    const int* edge_index = (const int*)d_in[1];
    const float* W1 = (const float*)d_in[2];
    const float* b1 = (const float*)d_in[3];
    const float* W2 = (const float*)d_in[4];
    const float* b2 = (const float*)d_in[5];
    const float* eps = (const float*)d_in[6];
    const float* ln_g = (const float*)d_in[7];
    const float* ln_b = (const float*)d_in[8];
    const float* pln_g = (const float*)d_in[9];
    const float* pln_b = (const float*)d_in[10];
    const float* pW = (const float*)d_in[11];
    const float* pb = (const float*)d_in[12];
    float* out = (float*)d_out;

    const int* src = edge_index;
    const int* dst = edge_index + N_EDGES;

    cudaFuncSetAttribute(k_mlp, cudaFuncAttributeMaxDynamicSharedMemorySize, SMEM_TC);
    cudaFuncSetAttribute(k_final, cudaFuncAttributeMaxDynamicSharedMemorySize, SMEM_TC);

    // prologue (fused) + CSR build
    k_pro<<<(N_NODES * D + 255) / 256, 256>>>(x, W1, W2, pW);
    k_hist<<<(N_EDGES + 255) / 256, 256>>>(dst);
    k_scan_local<<<NBLK, 1024>>>();
    k_scan_addtop<<<(N_NODES + 255) / 256, 256>>>();
    k_scatter<<<(N_EDGES + 255) / 256, 256>>>(src, dst);

    int gblocks = (N_NODES + 127) / 128;  // 782
    int ablocks = (N_NODES + 3) / 4;      // 25000
    for (int i = 0; i < NLAYER; i++) {
        k_agg<<<ablocks, 128>>>(eps, i);
        k_mlp<<<gblocks, 256, SMEM_TC>>>(i, b1 + (size_t)i * D, b2 + (size_t)i * D,
                                         ln_g + (size_t)i * D, ln_b + (size_t)i * D);
    }
    k_final<<<gblocks, 256, SMEM_TC>>>(pln_g, pln_b, pb, out);
}

// round 11
// speedup vs baseline: 3.1877x; 1.4338x over previous
#include <cuda_runtime.h>
#include <cuda_fp16.h>
#include <cstdint>
#include <math.h>

#define N_NODES 100000
#define N_EDGES 1600000
#define D 128
#define NLAYER 3
#define LN_EPS 1e-5f
#define NBLK 98  // (N_NODES + 1023) / 1024

// ---------------- scratch (static __device__; referenced ONLY in device code) ----------------
__device__ float g_h[N_NODES * D];        // residual stream (fp32 master)
__device__ float g_hsum[N_NODES * D];     // jumping-knowledge sum (fp32)
__device__ uint32_t g_hh[N_NODES * 64];   // fp16 mirror of h (gather input)
__device__ uint32_t g_zh[N_NODES * 64];   // z as packed half2 (GEMM A input)
__device__ int g_deg[N_NODES];            // zeroed by k_scan_addtop each call
__device__ int g_off[N_NODES + 1];
__device__ int g_cur[N_NODES];
__device__ int g_col[N_EDGES];
__device__ int g_bsum[128];
__device__ uint32_t g_bh[7 * 128 * 64];   // weights transposed [n][kpair], packed half2

// ================= helpers =================
__device__ __forceinline__ uint32_t packh2(float a, float b) {
    __half2 h = __floats2half2_rn(a, b);
    return *(uint32_t*)&h;
}
__device__ __forceinline__ float gelu_exact(float v) {
    return 0.5f * v * (1.0f + erff(v * 0.70710678118654752f));
}

// ================= smem layout =================
#define SAK 68
#define OFF_RED 67584                 // after the fp32 C tile (128 x 132 x 4)
#define SMEM_TC (OFF_RED + 3072)      // 70656 bytes -> 2 CTAs/SM
#define OFF_REDF 34816                // k_final: red arrays right after A tile
#define CSTRIDE 132

__device__ __forceinline__ void mma_f16(float c[4], uint32_t a0, uint32_t a1, uint32_t a2,
                                        uint32_t a3, uint32_t b0, uint32_t b1) {
    asm volatile(
        "mma.sync.aligned.m16n8k16.row.col.f32.f16.f16.f32 "
        "{%0,%1,%2,%3}, {%4,%5,%6,%7}, {%8,%9}, {%0,%1,%2,%3};"
        : "+f"(c[0]), "+f"(c[1]), "+f"(c[2]), "+f"(c[3])
        : "r"(a0), "r"(a1), "r"(a2), "r"(a3), "r"(b0), "r"(b1));
}

// run 8 k-steps of 128x128 MMA from smem A (SAK stride) + global B
__device__ __forceinline__ void mma_tile(const uint32_t* As, const uint32_t* Bg, int mw,
                                         int nw, int g, int tg, float c[4][4][4]) {
#pragma unroll
    for (int mt = 0; mt < 4; mt++)
#pragma unroll
        for (int nt = 0; nt < 4; nt++)
#pragma unroll
            for (int e = 0; e < 4; e++) c[mt][nt][e] = 0.f;
#pragma unroll
    for (int ks = 0; ks < 8; ks++) {
        int kw = ks * 8 + tg;
        uint32_t a[4][4];
#pragma unroll
        for (int mt = 0; mt < 4; mt++) {
            int r0 = (mw + mt * 16 + g) * SAK;
            a[mt][0] = As[r0 + kw];
            a[mt][1] = As[r0 + 8 * SAK + kw];
            a[mt][2] = As[r0 + kw + 4];
            a[mt][3] = As[r0 + 8 * SAK + kw + 4];
        }
        uint32_t b[4][2];
#pragma unroll
        for (int nt = 0; nt < 4; nt++) {
            int n0 = (nw + nt * 8 + g) << 6;
            b[nt][0] = __ldg(&Bg[n0 + kw]);
            b[nt][1] = __ldg(&Bg[n0 + kw + 4]);
        }
#pragma unroll
        for (int mt = 0; mt < 4; mt++)
#pragma unroll
            for (int nt = 0; nt < 4; nt++)
                mma_f16(c[mt][nt], a[mt][0], a[mt][1], a[mt][2], a[mt][3], b[nt][0], b[nt][1]);
    }
}

// ================= fused prologue: init h/hh, hist, convert weights =================
// g_deg is guaranteed zero on entry (static init on first call; k_scan_addtop
// re-zeroes it every call) -> hist can run here.
__global__ void k_pro(const float* __restrict__ x, const int* __restrict__ dst,
                      const float* __restrict__ W1, const float* __restrict__ W2,
                      const float* __restrict__ pW) {
    int i = blockIdx.x * blockDim.x + threadIdx.x;
    if (i < N_NODES * D) g_h[i] = x[i];
    if (i < N_NODES * 64) g_hh[i] = packh2(x[2 * i], x[2 * i + 1]);
    if (i < N_EDGES) atomicAdd(&g_deg[__ldg(&dst[i])], 1);
    if (i < 7 * 128 * 64) {
        int mat = i >> 13;
        int rem = i & 8191;
        int n = rem >> 6;
        int kw = rem & 63;
        const float* Bw = (mat < 3) ? (W1 + (size_t)mat * 16384)
                                    : ((mat < 6) ? (W2 + (size_t)(mat - 3) * 16384) : pW);
        float v0 = __ldg(&Bw[(size_t)(2 * kw) * 128 + n]);
        float v1 = __ldg(&Bw[(size_t)(2 * kw + 1) * 128 + n]);
        g_bh[i] = packh2(v0, v1);
    }
}

// ================= CSR build =================
__global__ void k_scan_local() {
    __shared__ int s[1024];
    int i = blockIdx.x * 1024 + threadIdx.x;
    int v = (i < N_NODES) ? g_deg[i] : 0;
    s[threadIdx.x] = v;
    __syncthreads();
#pragma unroll
    for (int off = 1; off < 1024; off <<= 1) {
        int t = (threadIdx.x >= off) ? s[threadIdx.x - off] : 0;
        __syncthreads();
        s[threadIdx.x] += t;
        __syncthreads();
    }
    if (i < N_NODES) g_off[i] = s[threadIdx.x] - v;
    if (threadIdx.x == 1023) g_bsum[blockIdx.x] = s[1023];
}

// adds top-level prefix, seeds g_cur, zeroes g_deg for the NEXT call,
// and writes the off[N] sentinel (k_agg uses off-diffs instead of deg).
__global__ void k_scan_addtop() {
    __shared__ int sp[NBLK + 1];
    __shared__ int sb[NBLK];
    if (threadIdx.x < NBLK) sb[threadIdx.x] = g_bsum[threadIdx.x];
    __syncthreads();
    if (threadIdx.x == 0) {
        int run = 0;
        for (int b = 0; b < NBLK; b++) {
            sp[b] = run;
            run += sb[b];
        }
    }
    __syncthreads();
    int i = blockIdx.x * blockDim.x + threadIdx.x;
    if (i < N_NODES) {
        int o = g_off[i] + sp[i >> 10];
        g_off[i] = o;
        g_cur[i] = o;
        g_deg[i] = 0;
    }
    if (i == 0) g_off[N_NODES] = N_EDGES;
}

__global__ void k_scatter(const int* __restrict__ src, const int* __restrict__ dst) {
    int e = blockIdx.x * blockDim.x + threadIdx.x;
    if (e < N_EDGES) {
        int d = dst[e];
        int p = atomicAdd(&g_cur[d], 1);
        g_col[p] = src[e];
    }
}

// ================= aggregation: warp per node, fp16 gather, fp32 accumulate =================
__global__ __launch_bounds__(128) void k_agg(const float* __restrict__ eps, int layer) {
    int wid = threadIdx.x >> 5, lane = threadIdx.x & 31;
    int n = blockIdx.x * 4 + wid;
    if (n >= N_NODES) return;
    float e1 = 1.0f + __ldg(&eps[layer]);
    float4 self = __ldg(&((const float4*)g_h)[(size_t)n * 32 + lane]);
    float4 acc;
    acc.x = self.x * e1;
    acc.y = self.y * e1;
    acc.z = self.z * e1;
    acc.w = self.w * e1;
    int beg = g_off[n];
    int cnt = g_off[n + 1] - beg;
    const uint2* hh2 = (const uint2*)g_hh;
    for (int base = 0; base < cnt; base += 32) {
        int m = min(32, cnt - base);
        int id = (lane < m) ? g_col[beg + base + lane] : 0;
        int j = 0;
        for (; j + 8 <= m; j += 8) {
            uint2 t[8];
#pragma unroll
            for (int q = 0; q < 8; q++) {
                int nb = __shfl_sync(0xffffffffu, id, j + q);
                t[q] = __ldg(&hh2[(size_t)nb * 32 + lane]);
            }
#pragma unroll
            for (int q = 0; q < 8; q++) {
                float2 f0 = __half22float2(*reinterpret_cast<const __half2*>(&t[q].x));
                float2 f1 = __half22float2(*reinterpret_cast<const __half2*>(&t[q].y));
                acc.x += f0.x;
                acc.y += f0.y;
                acc.z += f1.x;
                acc.w += f1.y;
            }
        }
        for (; j < m; j++) {
            int nb = __shfl_sync(0xffffffffu, id, j);
            uint2 t = __ldg(&hh2[(size_t)nb * 32 + lane]);
            float2 f0 = __half22float2(*reinterpret_cast<const __half2*>(&t.x));
            float2 f1 = __half22float2(*reinterpret_cast<const __half2*>(&t.y));
            acc.x += f0.x;
            acc.y += f0.y;
            acc.z += f1.x;
            acc.w += f1.y;
        }
    }
    uint2 o = make_uint2(packh2(acc.x, acc.y), packh2(acc.z, acc.w));
    ((uint2*)g_zh)[(size_t)n * 32 + lane] = o;
}

// ================= fused per-layer MLP =================
// z1 = relu(z @ W1 + b1) stays in smem (fp16), then z2 = z1 @ W2 + b2,
// then LN + GELU + residual -> g_h (+fp16 mirror), g_hsum.
__global__ void __launch_bounds__(256, 2)
k_mlp(int li, const float* __restrict__ b1, const float* __restrict__ b2,
      const float* __restrict__ lng, const float* __restrict__ lnb) {
    extern __shared__ char sm[];
    const int tid = threadIdx.x;
    const int wid = tid >> 5;
    const int lane = tid & 31;
    const int bm = blockIdx.x * 128;
    const bool first = (li == 0);
    const bool last = (li == NLAYER - 1);
    uint32_t* As = (uint32_t*)sm;

    // --- stage z tile (packed fp16 copy) ---
#pragma unroll
    for (int i = 0; i < 8; i++) {
        int idx = tid + i * 256;  // uint4 units, 2048 total
        int m = idx >> 4;
        int wq = (idx & 15) << 2;
        uint4 v = make_uint4(0u, 0u, 0u, 0u);
        int gm = bm + m;
        if (gm < N_NODES) v = __ldg(&((const uint4*)g_zh)[(size_t)gm * 16 + (wq >> 2)]);
        *(uint4*)&As[m * SAK + wq] = v;
    }
    __syncthreads();

    const int g = lane >> 2, tg = lane & 3;
    const int mw = (wid & 1) * 64;
    const int nw = (wid >> 1) * 32;
    float c[4][4][4];

    // --- GEMM1: z @ W1 ---
    mma_tile(As, g_bh + li * 8192, mw, nw, g, tg, c);
    __syncthreads();

    // --- relu(z1 + b1) -> As (fp16, in place) ---
#pragma unroll
    for (int nt = 0; nt < 4; nt++) {
        int col = nw + nt * 8 + tg * 2;
        float bz0 = __ldg(&b1[col]);
        float bz1 = __ldg(&b1[col + 1]);
        int wc = (col >> 1);
#pragma unroll
        for (int mt = 0; mt < 4; mt++) {
            int r0 = mw + mt * 16 + g;
            As[r0 * SAK + wc] =
                packh2(fmaxf(c[mt][nt][0] + bz0, 0.f), fmaxf(c[mt][nt][1] + bz1, 0.f));
            As[(r0 + 8) * SAK + wc] =
                packh2(fmaxf(c[mt][nt][2] + bz0, 0.f), fmaxf(c[mt][nt][3] + bz1, 0.f));
        }
    }
    __syncthreads();

    // --- GEMM2: z1 @ W2 ---
    mma_tile(As, g_bh + (3 + li) * 8192, mw, nw, g, tg, c);
    __syncthreads();

    // --- write fragments (+b2) to smem C tile ---
    float* Cs = (float*)sm;
#pragma unroll
    for (int nt = 0; nt < 4; nt++) {
        int col = nw + nt * 8 + tg * 2;
        float bz0 = __ldg(&b2[col]);
        float bz1 = __ldg(&b2[col + 1]);
#pragma unroll
        for (int mt = 0; mt < 4; mt++) {
            int r0 = mw + mt * 16 + g;
            Cs[r0 * CSTRIDE + col] = c[mt][nt][0] + bz0;
            Cs[r0 * CSTRIDE + col + 1] = c[mt][nt][1] + bz1;
            Cs[(r0 + 8) * CSTRIDE + col] = c[mt][nt][2] + bz0;
            Cs[(r0 + 8) * CSTRIDE + col + 1] = c[mt][nt][3] + bz1;
        }
    }
    __syncthreads();

    // --- LN stats ---
    float* red = (float*)(sm + OFF_RED);
    float* red2 = red + 256;
    float* rmean = red2 + 256;
    float* rrstd = rmean + 128;
    {
        int r = tid >> 1;
        int h0 = (tid & 1) * 64;
        float s = 0.f, s2 = 0.f;
#pragma unroll 8
        for (int cc = 0; cc < 64; cc++) {
            float v = Cs[r * CSTRIDE + h0 + cc];
            s += v;
            s2 += v * v;
        }
        red[r * 2 + (tid & 1)] = s;
        red2[r * 2 + (tid & 1)] = s2;
    }
    __syncthreads();
    if (tid < 128) {
        float S = red[tid * 2] + red[tid * 2 + 1];
        float S2 = red2[tid * 2] + red2[tid * 2 + 1];
        float mean = S * (1.0f / 128.0f);
        float var = S2 * (1.0f / 128.0f) - mean * mean;
        rmean[tid] = mean;
        rrstd[tid] = rsqrtf(var + LN_EPS);
    }
    __syncthreads();

    // --- LN + GELU + residual + mirrors (2 cols per thread) ---
#pragma unroll 4
    for (int i = 0; i < 32; i++) {
        int e = i * 256 + tid;  // col-pair index, 8192 total
        int r = e >> 6;
        int cp = e & 63;
        int cc = cp * 2;
        int gm = bm + r;
        if (gm < N_NODES) {
            float mean = rmean[r], rs = rrstd[r];
            float v0 = (Cs[r * CSTRIDE + cc] - mean) * rs * __ldg(&lng[cc]) + __ldg(&lnb[cc]);
            float v1 =
                (Cs[r * CSTRIDE + cc + 1] - mean) * rs * __ldg(&lng[cc + 1]) + __ldg(&lnb[cc + 1]);
            float g0 = gelu_exact(v0);
            float g1 = gelu_exact(v1);
            size_t gi = (size_t)gm * 128 + cc;
            float2 ho = *(float2*)(g_h + gi);
            float hn0 = g0 + ho.x;
            float hn1 = g1 + ho.y;
            *(float2*)(g_h + gi) = make_float2(hn0, hn1);
            if (!last) g_hh[(size_t)gm * 64 + cp] = packh2(hn0, hn1);
            if (first) {
                *(float2*)(g_hsum + gi) = make_float2(hn0, hn1);
            } else {
                float2 hs = *(float2*)(g_hsum + gi);
                hs.x += hn0;
                hs.y += hn1;
                *(float2*)(g_hsum + gi) = hs;
            }
        }
    }
}

// ================= fused final: row-LN(hsum) @ pW + pb -> out =================
__global__ void __launch_bounds__(256, 2)
k_final(const float* __restrict__ pg, const float* __restrict__ pbln,
        const float* __restrict__ pbias, float* __restrict__ out) {
    extern __shared__ char sm[];
    const int tid = threadIdx.x;
    const int wid = tid >> 5;
    const int lane = tid & 31;
    const int bm = blockIdx.x * 128;
    uint32_t* As = (uint32_t*)sm;
    float* red = (float*)(sm + OFF_REDF);
    float* red2 = red + 256;
    float* rmean = red2 + 256;
    float* rrstd = rmean + 128;

    {
        int r = tid >> 1;
        int h0 = (tid & 1) * 64;
        int gm = bm + r;
        float s = 0.f, s2 = 0.f;
        if (gm < N_NODES) {
#pragma unroll
            for (int cc = 0; cc < 64; cc += 4) {
                float4 v = *(const float4*)(g_hsum + (size_t)gm * 128 + h0 + cc);
                s += (v.x + v.y) + (v.z + v.w);
                s2 += (v.x * v.x + v.y * v.y) + (v.z * v.z + v.w * v.w);
            }
        }
        red[r * 2 + (tid & 1)] = s;
        red2[r * 2 + (tid & 1)] = s2;
    }
    __syncthreads();
    if (tid < 128) {
        float S = red[tid * 2] + red[tid * 2 + 1];
        float S2 = red2[tid * 2] + red2[tid * 2 + 1];
        float mean = S * (1.0f / 128.0f);
        float var = S2 * (1.0f / 128.0f) - mean * mean;
        rmean[tid] = mean;
        rrstd[tid] = rsqrtf(var + LN_EPS);
    }
    __syncthreads();

#pragma unroll
    for (int i = 0; i < 16; i++) {
        int idx = tid + i * 256;
        int m = idx >> 5;
        int u = idx & 31;
        int gm = bm + m;
        float4 v = make_float4(0.f, 0.f, 0.f, 0.f);
        if (gm < N_NODES) v = *(const float4*)(g_hsum + (size_t)gm * 128 + 4 * u);
        float mean = rmean[m], rs = rrstd[m];
        float4 g4 = __ldg(&((const float4*)pg)[u]);
        float4 b4 = __ldg(&((const float4*)pbln)[u]);
        float o0 = (v.x - mean) * rs * g4.x + b4.x;
        float o1 = (v.y - mean) * rs * g4.y + b4.y;
        float o2 = (v.z - mean) * rs * g4.z + b4.z;
        float o3 = (v.w - mean) * rs * g4.w + b4.w;
        *(uint2*)&As[m * SAK + 2 * u] = make_uint2(packh2(o0, o1), packh2(o2, o3));
    }
    __syncthreads();

    const int g = lane >> 2, tg = lane & 3;
    const int mw = (wid & 1) * 64;
    const int nw = (wid >> 1) * 32;
    float c[4][4][4];
    mma_tile(As, g_bh + 6 * 8192, mw, nw, g, tg, c);
    __syncthreads();

    float* Cs = (float*)sm;
#pragma unroll
    for (int nt = 0; nt < 4; nt++) {
        int col = nw + nt * 8 + tg * 2;
        float bz0 = __ldg(&pbias[col]);
        float bz1 = __ldg(&pbias[col + 1]);
#pragma unroll
        for (int mt = 0; mt < 4; mt++) {
            int r0 = mw + mt * 16 + g;
            Cs[r0 * CSTRIDE + col] = c[mt][nt][0] + bz0;
            Cs[r0 * CSTRIDE + col + 1] = c[mt][nt][1] + bz1;
            Cs[(r0 + 8) * CSTRIDE + col] = c[mt][nt][2] + bz0;
            Cs[(r0 + 8) * CSTRIDE + col + 1] = c[mt][nt][3] + bz1;
        }
    }
    __syncthreads();
#pragma unroll
    for (int i = 0; i < 16; i++) {
        int idx = tid + i * 256;
        int m = idx >> 5;
        int c4 = (idx & 31) << 2;
        int gm = bm + m;
        if (gm < N_NODES) {
            float4 o;
            o.x = Cs[m * CSTRIDE + c4];
            o.y = Cs[m * CSTRIDE + c4 + 1];
            o.z = Cs[m * CSTRIDE + c4 + 2];
            o.w = Cs[m * CSTRIDE + c4 + 3];
            *(float4*)(out + (size_t)gm * 128 + c4) = o;
        }
    }
}

// ================= launch =================
extern "C" void kernel_launch(void* const* d_in, const int* in_sizes, int n_in,
                              void* d_out, int out_size) {
    const float* x = (const float*)d_in[0];
    const int* edge_index = (const int*)d_in[1];
    const float* W1 = (const float*)d_in[2];
    const float* b1 = (const float*)d_in[3];
    const float* W2 = (const float*)d_in[4];
    const float* b2 = (const float*)d_in[5];
    const float* eps = (const float*)d_in[6];
    const float* ln_g = (const float*)d_in[7];
    const float* ln_b = (const float*)d_in[8];
    const float* pln_g = (const float*)d_in[9];
    const float* pln_b = (const float*)d_in[10];
    const float* pW = (const float*)d_in[11];
    const float* pb = (const float*)d_in[12];
    float* out = (float*)d_out;

    const int* src = edge_index;
    const int* dst = edge_index + N_EDGES;

    cudaFuncSetAttribute(k_mlp, cudaFuncAttributeMaxDynamicSharedMemorySize, SMEM_TC);
    cudaFuncSetAttribute(k_final, cudaFuncAttributeMaxDynamicSharedMemorySize, SMEM_TC);

    // prologue (init + hist fused) + CSR build
    k_pro<<<(N_NODES * D + 255) / 256, 256>>>(x, dst, W1, W2, pW);
    k_scan_local<<<NBLK, 1024>>>();
    k_scan_addtop<<<(N_NODES + 255) / 256, 256>>>();
    k_scatter<<<(N_EDGES + 255) / 256, 256>>>(src, dst);

    int gblocks = (N_NODES + 127) / 128;  // 782
    int ablocks = (N_NODES + 3) / 4;      // 25000
    for (int i = 0; i < NLAYER; i++) {
        k_agg<<<ablocks, 128>>>(eps, i);
        k_mlp<<<gblocks, 256, SMEM_TC>>>(i, b1 + (size_t)i * D, b2 + (size_t)i * D,
                                         ln_g + (size_t)i * D, ln_b + (size_t)i * D);
    }
    k_final<<<gblocks, 256, SMEM_TC>>>(pln_g, pln_b, pb, out);
}